// round 10
// baseline (speedup 1.0000x reference)
#include <cuda_runtime.h>
#include <cstdint>

// out[n] = embedding[hash(trunc(x[n]*128))]  (reference's xf==0 collapses the
// trilerp to corner 0, weight 1; bit-exact).
// hash = (u0 ^ u1*2654435761 ^ u2*805459861) & (2^19 - 1)
//
// R10: role-specialized blocks. Two independent gather engines exist:
//   - L1tex/LDG: capped ~0.36 random rows/cyc/SM (miss-queue), burns no ALU
//   - TMA bulk:  engine 1.7 cyc/op, but per-lane issue costs ~2.6 cyc/op of
//     SM ALU/issue slots (R9 measurement)
// Run both at once with PURE blocks: bid%3==2 -> TMA block (1024 pts, 32KB
// tile, 4 bulk32 ops/thread), else LDG block (512 pts, R3 pair-gather).
// 2L+1T groups split points exactly 50/50. CTA->SM stride ~148 === 1 (mod 3)
// so each SM's resident blocks alternate roles -> both resources saturate,
// no phase coupling.

static constexpr unsigned P1 = 2654435761u;
static constexpr unsigned P2 = 805459861u;
static constexpr unsigned HASH_MASK = 524288u - 1u;  // 2^19
static constexpr int THREADS = 256;
static constexpr int LDG_PTS = 512;
static constexpr int TMA_PTS = 1024;
static constexpr int GROUP_PTS = 2 * LDG_PTS + TMA_PTS;  // 2048

__device__ __forceinline__ unsigned hash3f(float a, float b, float c)
{
    unsigned u0 = (unsigned)__float2int_rz(a * 128.0f);
    unsigned u1 = (unsigned)__float2int_rz(b * 128.0f);
    unsigned u2 = (unsigned)__float2int_rz(c * 128.0f);
    return (u0 ^ (u1 * P1) ^ (u2 * P2)) & HASH_MASK;
}

__global__ void __launch_bounds__(THREADS)
hashgrid_roles_kernel(const float* __restrict__ x,
                      const float4* __restrict__ emb,  // [H][2] float4
                      float4* __restrict__ out,        // [N][2] float4
                      int n_ldg_total)                 // pts in LDG region
{
    __shared__ __align__(128) float4 tile[TMA_PTS * 2];  // 32 KB
    __shared__ __align__(8) unsigned long long mbar;

    const int bid = blockIdx.x;
    const int g   = bid / 3;
    const int r   = bid % 3;
    const int tid = threadIdx.x;

    if (r == 2) {
        // ================= TMA block: 1024 pts =================
        unsigned bar_a  = (unsigned)__cvta_generic_to_shared(&mbar);
        unsigned tile_a = (unsigned)__cvta_generic_to_shared(tile);

        if (tid == 0) {
            asm volatile("mbarrier.init.shared.b64 [%0], 1;"
                         :: "r"(bar_a) : "memory");
            asm volatile("mbarrier.arrive.expect_tx.shared.b64 _, [%0], %1;"
                         :: "r"(bar_a), "r"(TMA_PTS * 32) : "memory");
        }
        __syncthreads();

        const size_t base_pt = (size_t)n_ldg_total + (size_t)g * TMA_PTS;
        const char* embb = (const char*)emb;

        {
            // 4 consecutive points: 12 floats = 3 float4 (base_pt*3 % 4 == 0)
            const float4* x4 = (const float4*)x;
            size_t xb = base_pt * 3 / 4 + 3 * (size_t)tid;
            float4 a = __ldg(&x4[xb + 0]);
            float4 b = __ldg(&x4[xb + 1]);
            float4 c = __ldg(&x4[xb + 2]);

            unsigned h0 = hash3f(a.x, a.y, a.z);
            unsigned h1 = hash3f(a.w, b.x, b.y);
            unsigned h2 = hash3f(b.z, b.w, c.x);
            unsigned h3 = hash3f(c.y, c.z, c.w);

            unsigned dst = tile_a + (unsigned)tid * 128u;
#define BULK32(H, OFF)                                                        \
            asm volatile(                                                     \
                "cp.async.bulk.shared::cta.global"                            \
                ".mbarrier::complete_tx::bytes [%0], [%1], 32, [%2];"         \
                :: "r"(dst + (OFF)),                                          \
                   "l"(embb + (size_t)(H) * 32u), "r"(bar_a) : "memory")
            BULK32(h0, 0u);
            BULK32(h1, 32u);
            BULK32(h2, 64u);
            BULK32(h3, 96u);
#undef BULK32
        }

        asm volatile(
            "{\n\t"
            ".reg .pred P;\n\t"
            "WAIT_%=:\n\t"
            "mbarrier.try_wait.parity.acquire.cta.shared::cta.b64 P, [%0], 0, 0x989680;\n\t"
            "@P bra.uni DONE_%=;\n\t"
            "bra.uni WAIT_%=;\n\t"
            "DONE_%=:\n\t"
            "}"
            :: "r"(bar_a) : "memory");

        float4* o4 = out + base_pt * 2;
#pragma unroll
        for (int k = 0; k < 8; k++)
            o4[tid + 256 * k] = tile[tid + 256 * k];
    } else {
        // ================= LDG block: 512 pts (R3 pair-gather) =============
        int l    = 2 * g + r;           // LDG block index
        int w    = tid >> 5;
        int lane = tid & 31;
        int qw   = lane >> 1;
        int half = lane & 1;
        size_t base = (size_t)l * LDG_PTS + (size_t)w * 64 + qw;

        float xv[4][3];
#pragma unroll
        for (int k = 0; k < 4; k++) {
            size_t p = base + 16 * k;
            xv[k][0] = x[3 * p + 0];
            xv[k][1] = x[3 * p + 1];
            xv[k][2] = x[3 * p + 2];
        }
        unsigned h[4];
#pragma unroll
        for (int k = 0; k < 4; k++)
            h[k] = hash3f(xv[k][0], xv[k][1], xv[k][2]);

        float4 v[4];
#pragma unroll
        for (int k = 0; k < 4; k++)
            v[k] = __ldg(&emb[2 * h[k] + half]);
#pragma unroll
        for (int k = 0; k < 4; k++) {
            size_t p = base + 16 * k;
            out[2 * p + half] = v[k];
        }
    }
}

// ---------------- fallback (proven R3) for non-multiple sizes ----------------

__global__ void __launch_bounds__(THREADS)
hashgrid_gather_ilp4_kernel(const float* __restrict__ x,
                            const float4* __restrict__ emb,
                            float4* __restrict__ out,
                            int n)
{
    int tid  = threadIdx.x;
    int w    = tid >> 5;
    int lane = tid & 31;
    int qw   = lane >> 1;
    int half = lane & 1;
    int base = blockIdx.x * LDG_PTS + w * 64 + qw;

    float xv[4][3];
#pragma unroll
    for (int k = 0; k < 4; k++) {
        int p = base + 16 * k;
        if (p < n) {
            xv[k][0] = x[3 * p + 0];
            xv[k][1] = x[3 * p + 1];
            xv[k][2] = x[3 * p + 2];
        }
    }
    unsigned h[4];
#pragma unroll
    for (int k = 0; k < 4; k++)
        h[k] = hash3f(xv[k][0], xv[k][1], xv[k][2]);

    float4 v[4];
#pragma unroll
    for (int k = 0; k < 4; k++)
        if (base + 16 * k < n) v[k] = __ldg(&emb[2 * h[k] + half]);
#pragma unroll
    for (int k = 0; k < 4; k++) {
        int p = base + 16 * k;
        if (p < n) out[2 * p + half] = v[k];
    }
}

extern "C" void kernel_launch(void* const* d_in, const int* in_sizes, int n_in,
                              void* d_out, int out_size)
{
    const float*  x   = (const float*)d_in[0];
    const float4* emb = (const float4*)d_in[1];
    float4*       out = (float4*)d_out;

    int n = in_sizes[0] / 3;  // N_POINTS

    if (n % GROUP_PTS == 0) {
        int groups = n / GROUP_PTS;          // 1024
        int blocks = groups * 3;             // 3072
        int n_ldg_total = groups * 2 * LDG_PTS;  // 1,048,576
        hashgrid_roles_kernel<<<blocks, THREADS>>>(x, emb, out, n_ldg_total);
    } else {
        int blocks = (n + LDG_PTS - 1) / LDG_PTS;
        hashgrid_gather_ilp4_kernel<<<blocks, THREADS>>>(x, emb, out, n);
    }
}

// round 11
// speedup vs baseline: 1.3094x; 1.3094x over previous
#include <cuda_runtime.h>
#include <cstdint>

// out[n] = embedding[hash(trunc(x[n]*128))]  (reference's xf==0 collapses the
// trilerp to corner 0, weight 1; bit-exact).
// hash = (u0 ^ u1*2654435761 ^ u2*805459861) & (2^19 - 1)
//
// R11: warp-specialized hybrid, ONE block type (fixes R10's occupancy/mixing
// failure). Per 256-thread block, 1024 pts:
//   warps 0-3: hash 512 pts, fire 512 cp.async.bulk 32B row gathers into a
//              16KB smem tile (TMA engine + ALU pipe), wait mbarrier, flush.
//   warps 4-7: R3 LDG pair-gather for the other 512 pts (L1 miss queue),
//              store directly, never touch the barrier -> full overlap.
// The two gather engines burn disjoint resources (L1 miss queue vs
// ALU/MIO + TMA engine) and are both fed from inside every block.

static constexpr unsigned P1 = 2654435761u;
static constexpr unsigned P2 = 805459861u;
static constexpr unsigned HASH_MASK = 524288u - 1u;  // 2^19
static constexpr int THREADS = 256;
static constexpr int PTS_PER_BLOCK = 1024;
static constexpr int TMA_HALF = 512;

__device__ __forceinline__ unsigned hash3f(float a, float b, float c)
{
    unsigned u0 = (unsigned)__float2int_rz(a * 128.0f);
    unsigned u1 = (unsigned)__float2int_rz(b * 128.0f);
    unsigned u2 = (unsigned)__float2int_rz(c * 128.0f);
    return (u0 ^ (u1 * P1) ^ (u2 * P2)) & HASH_MASK;
}

__global__ void __launch_bounds__(THREADS, 6)
hashgrid_warpspec_kernel(const float* __restrict__ x,
                         const float4* __restrict__ emb,  // [H][2] float4
                         float4* __restrict__ out)        // [N][2] float4
{
    __shared__ __align__(128) float4 tile[TMA_HALF * 2];  // 16 KB
    __shared__ __align__(8) unsigned long long mbar;

    const int tid = threadIdx.x;
    const int wid = tid >> 5;
    const size_t base = (size_t)blockIdx.x * PTS_PER_BLOCK;

    unsigned bar_a = (unsigned)__cvta_generic_to_shared(&mbar);

    if (tid == 0) {
        asm volatile("mbarrier.init.shared.b64 [%0], 1;" :: "r"(bar_a) : "memory");
        asm volatile("mbarrier.arrive.expect_tx.shared.b64 _, [%0], %1;"
                     :: "r"(bar_a), "r"(TMA_HALF * 32) : "memory");
    }
    __syncthreads();

    if (wid < 4) {
        // ========== TMA warps: pts [base+512, base+1024) ==========
        unsigned tile_a = (unsigned)__cvta_generic_to_shared(tile);
        const char* embb = (const char*)emb;
        const float4* x4 = (const float4*)x;

        // 4 consecutive points: 12 floats = 3 float4 ((base+512)*3 % 4 == 0)
        size_t xb = (base + TMA_HALF) * 3 / 4 + 3 * (size_t)tid;
        float4 a = __ldg(&x4[xb + 0]);
        float4 b = __ldg(&x4[xb + 1]);
        float4 c = __ldg(&x4[xb + 2]);

        unsigned h0 = hash3f(a.x, a.y, a.z);
        unsigned h1 = hash3f(a.w, b.x, b.y);
        unsigned h2 = hash3f(b.z, b.w, c.x);
        unsigned h3 = hash3f(c.y, c.z, c.w);

        unsigned dst = tile_a + (unsigned)tid * 128u;
#define BULK32(H, OFF)                                                        \
        asm volatile(                                                         \
            "cp.async.bulk.shared::cta.global"                                \
            ".mbarrier::complete_tx::bytes [%0], [%1], 32, [%2];"             \
            :: "r"(dst + (OFF)),                                              \
               "l"(embb + (size_t)(H) * 32u), "r"(bar_a) : "memory")
        BULK32(h0, 0u);
        BULK32(h1, 32u);
        BULK32(h2, 64u);
        BULK32(h3, 96u);
#undef BULK32

        // wait for all 16 KB, then flush coalesced (8 float4 per thread)
        asm volatile(
            "{\n\t"
            ".reg .pred P;\n\t"
            "WAIT_%=:\n\t"
            "mbarrier.try_wait.parity.acquire.cta.shared::cta.b64 P, [%0], 0, 0x989680;\n\t"
            "@P bra.uni DONE_%=;\n\t"
            "bra.uni WAIT_%=;\n\t"
            "DONE_%=:\n\t"
            "}"
            :: "r"(bar_a) : "memory");

        float4* o4 = out + (base + TMA_HALF) * 2;
#pragma unroll
        for (int k = 0; k < 8; k++)
            o4[tid + 128 * k] = tile[tid + 128 * k];
    } else {
        // ========== LDG warps: pts [base, base+512), R3 pair-gather ========
        int w2   = wid - 4;          // 0..3, each owns 128 contiguous pts
        int lane = tid & 31;
        int qw   = lane >> 1;        // pair 0..15
        int half = lane & 1;
        size_t rb = base + (size_t)w2 * 128;

#pragma unroll
        for (int batch = 0; batch < 2; batch++) {
            size_t pb = rb + 64 * batch + qw;

            float xv[4][3];
#pragma unroll
            for (int k = 0; k < 4; k++) {
                size_t p = pb + 16 * k;
                xv[k][0] = x[3 * p + 0];
                xv[k][1] = x[3 * p + 1];
                xv[k][2] = x[3 * p + 2];
            }
            unsigned h[4];
#pragma unroll
            for (int k = 0; k < 4; k++)
                h[k] = hash3f(xv[k][0], xv[k][1], xv[k][2]);

            float4 v[4];
#pragma unroll
            for (int k = 0; k < 4; k++)
                v[k] = __ldg(&emb[2 * h[k] + half]);
#pragma unroll
            for (int k = 0; k < 4; k++) {
                size_t p = pb + 16 * k;
                out[2 * p + half] = v[k];
            }
        }
    }
}

// ---------------- fallback (proven R3) for non-multiple sizes ----------------

__global__ void __launch_bounds__(THREADS)
hashgrid_gather_ilp4_kernel(const float* __restrict__ x,
                            const float4* __restrict__ emb,
                            float4* __restrict__ out,
                            int n)
{
    int tid  = threadIdx.x;
    int w    = tid >> 5;
    int lane = tid & 31;
    int qw   = lane >> 1;
    int half = lane & 1;
    int base = blockIdx.x * 512 + w * 64 + qw;

    float xv[4][3];
#pragma unroll
    for (int k = 0; k < 4; k++) {
        int p = base + 16 * k;
        if (p < n) {
            xv[k][0] = x[3 * p + 0];
            xv[k][1] = x[3 * p + 1];
            xv[k][2] = x[3 * p + 2];
        }
    }
    unsigned h[4];
#pragma unroll
    for (int k = 0; k < 4; k++)
        h[k] = hash3f(xv[k][0], xv[k][1], xv[k][2]);

    float4 v[4];
#pragma unroll
    for (int k = 0; k < 4; k++)
        if (base + 16 * k < n) v[k] = __ldg(&emb[2 * h[k] + half]);
#pragma unroll
    for (int k = 0; k < 4; k++) {
        int p = base + 16 * k;
        if (p < n) out[2 * p + half] = v[k];
    }
}

extern "C" void kernel_launch(void* const* d_in, const int* in_sizes, int n_in,
                              void* d_out, int out_size)
{
    const float*  x   = (const float*)d_in[0];
    const float4* emb = (const float4*)d_in[1];
    float4*       out = (float4*)d_out;

    int n = in_sizes[0] / 3;  // N_POINTS

    if (n % PTS_PER_BLOCK == 0) {
        int blocks = n / PTS_PER_BLOCK;  // 2048
        hashgrid_warpspec_kernel<<<blocks, THREADS>>>(x, emb, out);
    } else {
        int blocks = (n + 511) / 512;
        hashgrid_gather_ilp4_kernel<<<blocks, THREADS>>>(x, emb, out, n);
    }
}

// round 12
// speedup vs baseline: 1.3712x; 1.0472x over previous
#include <cuda_runtime.h>
#include <cstdint>

// out[n] = embedding[hash(trunc(x[n]*128))]  (reference's xf==0 collapses the
// trilerp to corner 0, weight 1; bit-exact).
// hash = (u0 ^ u1*2654435761 ^ u2*805459861) & (2^19 - 1)
//
// R12: A/B probe of the per-SM outstanding-miss pool. All R2-R11 variants cap
// at ~0.36 random rows/cyc/SM regardless of path (LDG / cp.async / TMA bulk)
// -> one shared in-flight-request pool (~90 sectors @ ~250cyc L2 latency).
// Last untested partition: the nc/texture input path vs the generic cached
// path of L1TEX. Same octet kernel as R8 (best: 21.5us), but iteration 0
// gathers via ld.global.nc.b32 and iteration 1 via ld.global.ca.b32.
// Separate pools -> ~2x outstanding -> ~14us. Shared -> unchanged.

static constexpr unsigned P1 = 2654435761u;
static constexpr unsigned P2 = 805459861u;
static constexpr unsigned HASH_MASK = 524288u - 1u;  // 2^19
static constexpr int THREADS = 256;
static constexpr int PTS_PER_BLOCK = 512;            // 8 warps * 64 pts

__device__ __forceinline__ unsigned hash3f(float a, float b, float c)
{
    unsigned u0 = (unsigned)__float2int_rz(a * 128.0f);
    unsigned u1 = (unsigned)__float2int_rz(b * 128.0f);
    unsigned u2 = (unsigned)__float2int_rz(c * 128.0f);
    return (u0 ^ (u1 * P1) ^ (u2 * P2)) & HASH_MASK;
}

__device__ __forceinline__ float ld_nc(const float* p)
{
    float v;
    asm volatile("ld.global.nc.b32 %0, [%1];" : "=f"(v) : "l"(p));
    return v;
}

__device__ __forceinline__ float ld_ca(const float* p)
{
    float v;
    asm volatile("ld.global.ca.b32 %0, [%1];" : "=f"(v) : "l"(p));
    return v;
}

__global__ void __launch_bounds__(THREADS)
hashgrid_octet_ab_kernel(const float* __restrict__ x,
                         const float* __restrict__ embw,   // word view [H][8]
                         float* __restrict__ outw)         // word view [N][8]
{
    const int tid  = threadIdx.x;
    const int w    = tid >> 5;
    const int L    = tid & 31;
    const int sub  = L >> 3;   // which of 4 rows this lane helps gather
    const int word = L & 7;    // which 4B word of the 32B row

    const size_t wb = (size_t)blockIdx.x * PTS_PER_BLOCK + (size_t)w * 64;

    // ---- hash one point per lane, two iterations (64 pts per warp) ----
    unsigned h[2];
#pragma unroll
    for (int it = 0; it < 2; it++) {
        size_t p = wb + it * 32 + L;
        float a = x[3 * p + 0];
        float b = x[3 * p + 1];
        float c = x[3 * p + 2];
        h[it] = hash3f(a, b, c);
    }

    // ---- gather: 16 independent LDG.32, 4 rows per instruction.
    //      it=0 -> nc path, it=1 -> ca path (A/B of miss-queue pools) ----
    float v[16];
#pragma unroll
    for (int s = 0; s < 8; s++) {
        unsigned hs = __shfl_sync(0xFFFFFFFFu, h[0], 4 * s + sub);
        v[s] = ld_nc(&embw[(size_t)hs * 8 + word]);
    }
#pragma unroll
    for (int s = 0; s < 8; s++) {
        unsigned hs = __shfl_sync(0xFFFFFFFFu, h[1], 4 * s + sub);
        v[8 + s] = ld_ca(&embw[(size_t)hs * 8 + word]);
    }

    // ---- stores: each STG.32 writes 128B contiguous (4 pts) ----
#pragma unroll
    for (int it = 0; it < 2; it++) {
#pragma unroll
        for (int s = 0; s < 8; s++) {
            size_t p = wb + it * 32 + 4 * s + sub;
            outw[p * 8 + it * 8 + s - it * 8 + 0] = 0.0f;  // placeholder removed below
        }
    }
}

// NOTE: the store loop above was mangled during editing; the real kernel is
// below. (Kept deliberately simple and correct.)

__global__ void __launch_bounds__(THREADS)
hashgrid_octet_ab2_kernel(const float* __restrict__ x,
                          const float* __restrict__ embw,
                          float* __restrict__ outw)
{
    const int tid  = threadIdx.x;
    const int w    = tid >> 5;
    const int L    = tid & 31;
    const int sub  = L >> 3;
    const int word = L & 7;

    const size_t wb = (size_t)blockIdx.x * PTS_PER_BLOCK + (size_t)w * 64;

    unsigned h[2];
#pragma unroll
    for (int it = 0; it < 2; it++) {
        size_t p = wb + it * 32 + L;
        float a = x[3 * p + 0];
        float b = x[3 * p + 1];
        float c = x[3 * p + 2];
        h[it] = hash3f(a, b, c);
    }

    float v[16];
#pragma unroll
    for (int s = 0; s < 8; s++) {
        unsigned hs = __shfl_sync(0xFFFFFFFFu, h[0], 4 * s + sub);
        v[s] = ld_nc(&embw[(size_t)hs * 8 + word]);
    }
#pragma unroll
    for (int s = 0; s < 8; s++) {
        unsigned hs = __shfl_sync(0xFFFFFFFFu, h[1], 4 * s + sub);
        v[8 + s] = ld_ca(&embw[(size_t)hs * 8 + word]);
    }

#pragma unroll
    for (int it = 0; it < 2; it++) {
#pragma unroll
        for (int s = 0; s < 8; s++) {
            size_t p = wb + it * 32 + 4 * s + sub;
            outw[p * 8 + word] = v[it * 8 + s];
        }
    }
}

// ---------------- fallback (proven R3) for non-multiple sizes ----------------

__global__ void __launch_bounds__(THREADS)
hashgrid_gather_ilp4_kernel(const float* __restrict__ x,
                            const float4* __restrict__ emb,
                            float4* __restrict__ out,
                            int n)
{
    int tid  = threadIdx.x;
    int w    = tid >> 5;
    int lane = tid & 31;
    int qw   = lane >> 1;
    int half = lane & 1;
    int base = blockIdx.x * PTS_PER_BLOCK + w * 64 + qw;

    float xv[4][3];
#pragma unroll
    for (int k = 0; k < 4; k++) {
        int p = base + 16 * k;
        if (p < n) {
            xv[k][0] = x[3 * p + 0];
            xv[k][1] = x[3 * p + 1];
            xv[k][2] = x[3 * p + 2];
        }
    }
    unsigned h[4];
#pragma unroll
    for (int k = 0; k < 4; k++)
        h[k] = hash3f(xv[k][0], xv[k][1], xv[k][2]);

    float4 v[4];
#pragma unroll
    for (int k = 0; k < 4; k++)
        if (base + 16 * k < n) v[k] = __ldg(&emb[2 * h[k] + half]);
#pragma unroll
    for (int k = 0; k < 4; k++) {
        int p = base + 16 * k;
        if (p < n) out[2 * p + half] = v[k];
    }
}

extern "C" void kernel_launch(void* const* d_in, const int* in_sizes, int n_in,
                              void* d_out, int out_size)
{
    const float* x   = (const float*)d_in[0];
    const float* emb = (const float*)d_in[1];
    float*       out = (float*)d_out;

    int n = in_sizes[0] / 3;  // N_POINTS

    if (n % PTS_PER_BLOCK == 0) {
        int blocks = n / PTS_PER_BLOCK;  // 4096
        hashgrid_octet_ab2_kernel<<<blocks, THREADS>>>(x, emb, out);
    } else {
        int blocks = (n + PTS_PER_BLOCK - 1) / PTS_PER_BLOCK;
        hashgrid_gather_ilp4_kernel<<<blocks, THREADS>>>(
            x, (const float4*)emb, (float4*)out, n);
    }
}

// round 14
// speedup vs baseline: 1.3979x; 1.0195x over previous
#include <cuda_runtime.h>
#include <cstdint>

// out[n] = embedding[hash(trunc(x[n]*128))]  (reference's xf==0 collapses the
// trilerp to corner 0, weight 1; bit-exact).
// hash = (u0 ^ u1*2654435761 ^ u2*805459861) & (2^19 - 1)
//
// R14: R13 retry with the legal encoding. sm_103 ptxas rejects a bare
// .L2::evict_last qualifier on scalar loads; use createpolicy.fractional +
// ld.global.nc.L2::cache_hint.b32 instead (policy in a b64 register).
//   - gathers: evict_last policy (pin 16MB table in L2)
//   - x loads / out stores: .cs (streaming, evict-first)
// Kernel is at the per-SM outstanding-request wall; throughput = pool/latency,
// so keeping table lines L2-resident (250 vs 577 cyc) buys proportional time.

static constexpr unsigned P1 = 2654435761u;
static constexpr unsigned P2 = 805459861u;
static constexpr unsigned HASH_MASK = 524288u - 1u;  // 2^19
static constexpr int THREADS = 256;
static constexpr int PTS_PER_BLOCK = 512;            // 8 warps * 64 pts

__device__ __forceinline__ unsigned hash3f(float a, float b, float c)
{
    unsigned u0 = (unsigned)__float2int_rz(a * 128.0f);
    unsigned u1 = (unsigned)__float2int_rz(b * 128.0f);
    unsigned u2 = (unsigned)__float2int_rz(c * 128.0f);
    return (u0 ^ (u1 * P1) ^ (u2 * P2)) & HASH_MASK;
}

__device__ __forceinline__ float ld_table(const float* p, unsigned long long pol)
{
    float v;
    asm volatile("ld.global.nc.L2::cache_hint.b32 %0, [%1], %2;"
                 : "=f"(v) : "l"(p), "l"(pol));
    return v;
}

__device__ __forceinline__ float ld_stream(const float* p)
{
    float v;
    asm volatile("ld.global.cs.b32 %0, [%1];" : "=f"(v) : "l"(p));
    return v;
}

__device__ __forceinline__ void st_stream(float* p, float v)
{
    asm volatile("st.global.cs.b32 [%0], %1;" :: "l"(p), "f"(v) : "memory");
}

__global__ void __launch_bounds__(THREADS)
hashgrid_octet_pin_kernel(const float* __restrict__ x,
                          const float* __restrict__ embw,   // word view [H][8]
                          float* __restrict__ outw)         // word view [N][8]
{
    const int tid  = threadIdx.x;
    const int w    = tid >> 5;
    const int L    = tid & 31;
    const int sub  = L >> 3;   // which of 4 rows this lane helps gather
    const int word = L & 7;    // which 4B word of the 32B row

    // evict_last policy for the embedding table
    unsigned long long pol;
    asm volatile("createpolicy.fractional.L2::evict_last.b64 %0, 1.0;"
                 : "=l"(pol));

    const size_t wb = (size_t)blockIdx.x * PTS_PER_BLOCK + (size_t)w * 64;

    // ---- hash one point per lane, two iterations (64 pts per warp) ----
    unsigned h[2];
#pragma unroll
    for (int it = 0; it < 2; it++) {
        size_t p = wb + it * 32 + L;
        float a = ld_stream(&x[3 * p + 0]);
        float b = ld_stream(&x[3 * p + 1]);
        float c = ld_stream(&x[3 * p + 2]);
        h[it] = hash3f(a, b, c);
    }

    // ---- gather: 16 independent LDG.32, 4 rows per instruction,
    //      table lines pinned in L2 via evict_last policy ----
    float v[16];
#pragma unroll
    for (int it = 0; it < 2; it++) {
#pragma unroll
        for (int s = 0; s < 8; s++) {
            unsigned hs = __shfl_sync(0xFFFFFFFFu, h[it], 4 * s + sub);
            v[it * 8 + s] = ld_table(&embw[(size_t)hs * 8 + word], pol);
        }
    }

    // ---- stores: each STG.32 writes 128B contiguous (4 pts), evict-first ----
#pragma unroll
    for (int it = 0; it < 2; it++) {
#pragma unroll
        for (int s = 0; s < 8; s++) {
            size_t p = wb + it * 32 + 4 * s + sub;
            st_stream(&outw[p * 8 + word], v[it * 8 + s]);
        }
    }
}

// ---------------- fallback (proven R3) for non-multiple sizes ----------------

__global__ void __launch_bounds__(THREADS)
hashgrid_gather_ilp4_kernel(const float* __restrict__ x,
                            const float4* __restrict__ emb,
                            float4* __restrict__ out,
                            int n)
{
    int tid  = threadIdx.x;
    int w    = tid >> 5;
    int lane = tid & 31;
    int qw   = lane >> 1;
    int half = lane & 1;
    int base = blockIdx.x * PTS_PER_BLOCK + w * 64 + qw;

    float xv[4][3];
#pragma unroll
    for (int k = 0; k < 4; k++) {
        int p = base + 16 * k;
        if (p < n) {
            xv[k][0] = x[3 * p + 0];
            xv[k][1] = x[3 * p + 1];
            xv[k][2] = x[3 * p + 2];
        }
    }
    unsigned h[4];
#pragma unroll
    for (int k = 0; k < 4; k++)
        h[k] = hash3f(xv[k][0], xv[k][1], xv[k][2]);

    float4 v[4];
#pragma unroll
    for (int k = 0; k < 4; k++)
        if (base + 16 * k < n) v[k] = __ldg(&emb[2 * h[k] + half]);
#pragma unroll
    for (int k = 0; k < 4; k++) {
        int p = base + 16 * k;
        if (p < n) out[2 * p + half] = v[k];
    }
}

extern "C" void kernel_launch(void* const* d_in, const int* in_sizes, int n_in,
                              void* d_out, int out_size)
{
    const float* x   = (const float*)d_in[0];
    const float* emb = (const float*)d_in[1];
    float*       out = (float*)d_out;

    int n = in_sizes[0] / 3;  // N_POINTS

    if (n % PTS_PER_BLOCK == 0) {
        int blocks = n / PTS_PER_BLOCK;  // 4096
        hashgrid_octet_pin_kernel<<<blocks, THREADS>>>(x, emb, out);
    } else {
        int blocks = (n + PTS_PER_BLOCK - 1) / PTS_PER_BLOCK;
        hashgrid_gather_ilp4_kernel<<<blocks, THREADS>>>(
            x, (const float4*)emb, (float4*)out, n);
    }
}